// round 4
// baseline (speedup 1.0000x reference)
#include <cuda_runtime.h>

// onering_conv: out[n,o,b] = sum_{k,c} x[idx[n*7+k], c, b] * W[o, k*64+c] + bias[o]
// Shapes: N=163842 (runtime), C=64, B=2, K=7, O=64.
// NOTE: neigh_orders is int32 on device (JAX canonicalizes int64->int32 without x64).
//
// Persistent CTAs (<=148, grid-stride), 256 threads. W^T staged to smem once
// per CTA. Per 16-vertex tile: gather 7 neighbor rows/vertex into smem with
// the batch pair duplicated (b0,b0,b1,b1) so the inner product runs on packed
// fma.rn.f32x2 (2 FP32 FMAs per instruction on sm_103a).

#define N_TILE   16
#define CFEAT    64
#define BATCH    2
#define KNEI     7
#define OFEAT    64
#define KCDIM    (KNEI * CFEAT)        // 448
#define THREADS  256
#define XD_STRIDE 1796                 // 448*4 + 4 pad floats -> 4-bank offset per vertex row
#define SMEM_BYTES ((KCDIM * OFEAT + N_TILE * XD_STRIDE) * 4)   // 229632 <= 232448 opt-in

typedef unsigned long long ull;

__device__ __forceinline__ ull fma2(ull a, ull b, ull c) {
    ull d;
    asm("fma.rn.f32x2 %0, %1, %2, %3;" : "=l"(d) : "l"(a), "l"(b), "l"(c));
    return d;
}
__device__ __forceinline__ ull pack2(float lo, float hi) {
    ull d;
    asm("mov.b64 %0, {%1, %2};" : "=l"(d) : "f"(lo), "f"(hi));
    return d;
}
__device__ __forceinline__ float2 unpack2(ull v) {
    float2 f;
    asm("mov.b64 {%0, %1}, %2;" : "=f"(f.x), "=f"(f.y) : "l"(v));
    return f;
}

__global__ __launch_bounds__(THREADS, 1)
void onering_conv_kernel(const float* __restrict__ x,
                         const int* __restrict__ neigh,
                         const float* __restrict__ W,
                         const float* __restrict__ bias,
                         float* __restrict__ out,
                         int nvert, int ntiles)
{
    extern __shared__ float smem[];
    float* sh_wT = smem;                         // [448][64]  (kc-major, o contiguous)
    float* sh_xd = smem + KCDIM * OFEAT;         // [16][1796] (b0,b0,b1,b1 per kc)

    const int tid = threadIdx.x;

    // ---- Stage W transposed: sh_wT[kc*64 + o] = W[o*448 + kc]  (once per CTA) ----
    for (int j = tid; j < KCDIM * OFEAT; j += THREADS) {
        int kc = j >> 6;
        int o  = j & 63;
        sh_wT[j] = W[o * KCDIM + kc];
    }

    const int v      = tid >> 4;    // vertex within tile, 0..15
    const int lane_o = tid & 15;    // output quad: o in [4*lane_o, 4*lane_o+3]

    float2 b01 = *(const float2*)(bias + lane_o * 4);
    float2 b23 = *(const float2*)(bias + lane_o * 4 + 2);
    const ull bias0 = pack2(b01.x, b01.y);
    const ull bias1 = pack2(b23.x, b23.y);

    __syncthreads();

    for (int tile = blockIdx.x; tile < ntiles; tile += gridDim.x) {
        const int base = tile * N_TILE;
        const int rem  = (nvert - base < N_TILE) ? (nvert - base) : N_TILE;

        // ---- Gather + duplicate: rem vertices x 7 neighbor rows x 64 c ----
        // Consecutive threads hit consecutive c within a neighbor row ->
        // coalesced float2 LDG (x is L2-resident); STS.128 conflict-free.
        for (int j = tid; j < rem * KCDIM; j += THREADS) {
            int gv = j / KCDIM;
            int kc = j - gv * KCDIM;
            int k  = kc >> 6;
            int c  = kc & 63;
            int row = neigh[(base + gv) * KNEI + k];
            // safety clamp: converts any bad index into measurable wrong output
            row = (row < 0) ? 0 : ((row >= nvert) ? nvert - 1 : row);
            float2 xv = *(const float2*)(x + (long long)row * (CFEAT * BATCH) + c * BATCH);
            *(float4*)(sh_xd + gv * XD_STRIDE + kc * 4) =
                make_float4(xv.x, xv.x, xv.y, xv.y);
        }
        __syncthreads();

        // ---- Inner product: per kc = 2x LDS.128 + 4x fma.rn.f32x2 ----
        if (v < rem) {
            ull a0 = bias0, a1 = bias0, a2 = bias1, a3 = bias1;
            const ulonglong2* xrow = (const ulonglong2*)(sh_xd + v * XD_STRIDE);
            const ulonglong2* wrow = (const ulonglong2*)(sh_wT + lane_o * 4);
            #pragma unroll 8
            for (int kc = 0; kc < KCDIM; kc++) {
                ulonglong2 xv = xrow[kc];        // (.x = (b0,b0), .y = (b1,b1))
                ulonglong2 wv = wrow[kc * 16];   // (.x = (w[o0],w[o1]), .y = (w[o2],w[o3]))
                a0 = fma2(wv.x, xv.x, a0);       // (o0,o1) @ b0
                a1 = fma2(wv.x, xv.y, a1);       // (o0,o1) @ b1
                a2 = fma2(wv.y, xv.x, a2);       // (o2,o3) @ b0
                a3 = fma2(wv.y, xv.y, a3);       // (o2,o3) @ b1
            }
            float2 f0 = unpack2(a0), f1 = unpack2(a1);
            float2 f2 = unpack2(a2), f3 = unpack2(a3);
            // out layout: n*128 + o*2 + b ; thread owns 8 contiguous floats
            float* op = out + (long long)(base + v) * (OFEAT * BATCH) + lane_o * 8;
            *(float4*)(op)     = make_float4(f0.x, f1.x, f0.y, f1.y);
            *(float4*)(op + 4) = make_float4(f2.x, f3.x, f2.y, f3.y);
        }
        __syncthreads();   // sh_xd is reused by the next tile's gather
    }
}

extern "C" void kernel_launch(void* const* d_in, const int* in_sizes, int n_in,
                              void* d_out, int out_size)
{
    const float* x     = (const float*)d_in[0];
    const int*   neigh = (const int*)d_in[1];     // int32 (JAX default canonicalization)
    const float* W     = (const float*)d_in[2];
    const float* bias  = (const float*)d_in[3];
    float*       out   = (float*)d_out;

    const int nvert  = in_sizes[0] / (CFEAT * BATCH);
    const int ntiles = (nvert + N_TILE - 1) / N_TILE;

    cudaFuncSetAttribute(onering_conv_kernel,
                         cudaFuncAttributeMaxDynamicSharedMemorySize, SMEM_BYTES);

    // Persistent grid: 148 CTAs covers any sm_103a part via the grid-stride loop.
    int blocks = (ntiles < 148) ? ntiles : 148;
    onering_conv_kernel<<<blocks, THREADS, SMEM_BYTES>>>(x, neigh, W, bias, out,
                                                         nvert, ntiles);
}

// round 7
// speedup vs baseline: 3.1172x; 3.1172x over previous
#include <cuda_runtime.h>
#include <cstdint>

// onering_conv via legacy tensor-core mma.sync (tf32), since tcgen05 PTX is
// rejected by this build's plain sm_103 target.
// out[n,o,b] = sum_{k,c} x[idx[n*7+k], c, b] * W[o, k*64+c] + bias[o]
// Per 32-vertex tile: A[64 x 448] (rows m = 2*v+b) @ W^T -> D[64 x 64].
// 16 warps: warp-tile 32x32, 4-way k-split (112 cols each), smem reduction.
//
// Smem layout tricks:
//  * column permutation within each 8-col block: p(w) = (w&3)*2 + (w>>2)
//    so fragment register pairs (a0,a2),(a1,a3),(b0,b1) are contiguous -> LDS.64
//  * XOR swizzle ^((row&3)<<3) -> conflict-free LDS.64 / STS.32 (verified per phase)
//  * inputs converted with cvt.rna.tf32.f32 at staging (round-to-nearest tf32)

#define KNEI    7
#define CFEAT   64
#define OFEAT   64
#define NV_TILE 32
#define M_ROWS  64              // 2 * NV_TILE
#define KC      448
#define THREADS 512

#define SM_BIAS 0
#define SM_A    1024                        // 64*448*4 = 114688 B
#define SM_W    (SM_A + M_ROWS*KC*4)        // 115712
#define SMEM_TOTAL (SM_W + OFEAT*KC*4)      // 230400 <= 232448 opt-in
#define SM_P    SM_A                        // partials overlay A: 4*64*64*4 = 65536 B

static __device__ __forceinline__ float to_tf32(float x) {
    float r;
    asm("cvt.rna.tf32.f32 %0, %1;" : "=f"(r) : "f"(x));
    return r;
}
// permuted column within row: blocks of 8, p(w) = (w&3)*2 + (w>>2)
static __device__ __forceinline__ int colperm(int kcol) {
    return (kcol & ~7) | ((kcol & 3) << 1) | ((kcol >> 2) & 1);
}
static __device__ __forceinline__ void mma_tf32(float* d, float2 aA, float2 aB, float2 b) {
    // operands: a0=aA.x (row r, col c), a1=aB.x (row r+8, c), a2=aA.y (r, c+4), a3=aB.y (r+8, c+4)
    asm volatile(
        "mma.sync.aligned.m16n8k8.row.col.f32.tf32.tf32.f32 "
        "{%0,%1,%2,%3}, {%4,%5,%6,%7}, {%8,%9}, {%0,%1,%2,%3};"
        : "+f"(d[0]), "+f"(d[1]), "+f"(d[2]), "+f"(d[3])
        : "r"(__float_as_uint(aA.x)), "r"(__float_as_uint(aB.x)),
          "r"(__float_as_uint(aA.y)), "r"(__float_as_uint(aB.y)),
          "r"(__float_as_uint(b.x)),  "r"(__float_as_uint(b.y)));
}

__global__ __launch_bounds__(THREADS, 1)
void onering_mma_kernel(const float* __restrict__ x,
                        const int* __restrict__ neigh,
                        const float* __restrict__ W,
                        const float* __restrict__ bias,
                        float* __restrict__ out,
                        int nvert, int ntiles)
{
    extern __shared__ char smem[];
    float* As   = (float*)(smem + SM_A);
    float* Ws   = (float*)(smem + SM_W);
    float* Ps   = (float*)(smem + SM_P);
    float* bi_s = (float*)(smem + SM_BIAS);

    const int tid  = threadIdx.x;
    const int wid  = tid >> 5;
    const int lane = tid & 31;
    const int r    = lane >> 2;      // 0..7
    const int c    = lane & 3;       // 0..3
    const uint32_t swz = (uint32_t)(r & 3) << 3;

    // warp placement: k-split, m-block, n-block
    const int ks = wid & 3;
    const int tm = (wid >> 2) & 1;
    const int tn = (wid >> 3) & 1;
    const int am0 = tm * 32 + r;     // A fragment row base (f adds 16, a1/a3 add 8)
    const int ob0 = tn * 32 + r;     // W fragment o base   (g adds 8)

    // ---- one-time staging: W (tf32, permuted+swizzled) and bias ----
    for (int j = tid; j < OFEAT * KC; j += THREADS) {
        int o = j / KC;
        int kcol = j - o * KC;
        int cp = colperm(kcol);
        Ws[o * KC + (cp ^ ((o & 3) << 3))] = to_tf32(W[j]);
    }
    if (tid < OFEAT) bi_s[tid] = bias[tid];
    __syncthreads();

    for (int tile = blockIdx.x; tile < ntiles; tile += gridDim.x) {
        const int base = tile * NV_TILE;
        const int rem  = (nvert - base < NV_TILE) ? (nvert - base) : NV_TILE;

        // ---- gather: A[m=2v+b][kcol=k*64+cc] = tf32(x[neigh[v,k]][cc*2+b]) ----
        // warp: 32 consecutive kcol -> coalesced 256B LDG, conflict-free STS.32
        const int glim = rem * KC;
        for (int e = tid; e < glim; e += THREADS) {
            int v    = e / KC;
            int kcol = e - v * KC;
            int k    = kcol >> 6;
            int cc   = kcol & 63;
            int rown = neigh[(base + v) * KNEI + k];
            rown = (rown < 0) ? 0 : ((rown >= nvert) ? nvert - 1 : rown);
            float2 xv = *(const float2*)(x + (size_t)rown * 128 + cc * 2);
            int cp = colperm(kcol);
            int m0 = 2 * v;
            As[m0 * KC + (cp ^ ((m0 & 3) << 3))]             = to_tf32(xv.x);
            As[(m0 + 1) * KC + (cp ^ (((m0 + 1) & 3) << 3))] = to_tf32(xv.y);
        }
        __syncthreads();

        // ---- mma mainloop: warp covers D[tm*32..+32][tn*32..+32], k in [ks*112, +112) ----
        float acc[2][4][4];
        #pragma unroll
        for (int f = 0; f < 2; f++)
            #pragma unroll
            for (int g = 0; g < 4; g++)
                #pragma unroll
                for (int q = 0; q < 4; q++) acc[f][g][q] = 0.0f;

        const float2* A2 = (const float2*)As;
        const float2* W2 = (const float2*)Ws;
        #pragma unroll 2
        for (int i = 0; i < 14; i++) {
            const int k0 = ks * 112 + i * 8;
            const uint32_t colp = (uint32_t)(k0 + 2 * c) ^ swz;   // even float index
            float2 fA[2][2];
            #pragma unroll
            for (int f = 0; f < 2; f++) {
                int m = am0 + f * 16;
                fA[f][0] = A2[((uint32_t)m * KC + colp) >> 1];        // (a0, a2)
                fA[f][1] = A2[((uint32_t)(m + 8) * KC + colp) >> 1];  // (a1, a3)
            }
            float2 fB[4];
            #pragma unroll
            for (int g = 0; g < 4; g++) {
                int o = ob0 + g * 8;
                fB[g] = W2[((uint32_t)o * KC + colp) >> 1];           // (b0, b1)
            }
            #pragma unroll
            for (int f = 0; f < 2; f++)
                #pragma unroll
                for (int g = 0; g < 4; g++)
                    mma_tf32(acc[f][g], fA[f][0], fA[f][1], fB[g]);
        }
        __syncthreads();   // all warps done reading A before partials overlay it

        // ---- store k-split partials: P[ks][m][n ^ ((m&3)<<3)] ----
        float2* P2 = (float2*)Ps;
        #pragma unroll
        for (int f = 0; f < 2; f++) {
            int m  = am0 + f * 16;              // d0/d1 row; d2/d3 at m+8
            #pragma unroll
            for (int g = 0; g < 4; g++) {
                uint32_t n0 = (uint32_t)(tn * 32 + g * 8 + 2 * c) ^ swz;  // even
                P2[((uint32_t)(ks * 4096 + m * 64) + n0) >> 1]       =
                    make_float2(acc[f][g][0], acc[f][g][1]);
                P2[((uint32_t)(ks * 4096 + (m + 8) * 64) + n0) >> 1] =
                    make_float2(acc[f][g][2], acc[f][g][3]);
            }
        }
        __syncthreads();

        // ---- reduce 4 partials + bias, write out (coalesced float4) ----
        // out float4 at lin: (o0,b0),(o0,b1),(o0+1,b0),(o0+1,b1); o0 even
        for (int j = tid; j < rem * 32; j += THREADS) {
            int lin = j * 4;
            int nl  = lin >> 7;
            int o0  = (lin & 127) >> 1;
            int mA  = 2 * nl, mB = mA + 1;
            uint32_t swA = (uint32_t)(mA & 3) << 3;
            uint32_t swB = (uint32_t)(mB & 3) << 3;
            float vAx = 0.f, vBx = 0.f, vAy = 0.f, vBy = 0.f;
            #pragma unroll
            for (int s = 0; s < 4; s++) {
                const float* Pp = Ps + s * 4096;
                vAx += Pp[mA * 64 + ((uint32_t)o0 ^ swA)];
                vBx += Pp[mB * 64 + ((uint32_t)o0 ^ swB)];
                vAy += Pp[mA * 64 + ((uint32_t)(o0 + 1) ^ swA)];
                vBy += Pp[mB * 64 + ((uint32_t)(o0 + 1) ^ swB)];
            }
            float4 vv = make_float4(vAx + bi_s[o0], vBx + bi_s[o0],
                                    vAy + bi_s[o0 + 1], vBy + bi_s[o0 + 1]);
            *(float4*)(out + (size_t)base * 128 + lin) = vv;
        }
        __syncthreads();   // P / A region reused by next tile's gather
    }
}

extern "C" void kernel_launch(void* const* d_in, const int* in_sizes, int n_in,
                              void* d_out, int out_size)
{
    const float* x     = (const float*)d_in[0];
    const int*   neigh = (const int*)d_in[1];     // int32 (JAX canonicalization)
    const float* W     = (const float*)d_in[2];
    const float* bias  = (const float*)d_in[3];
    float*       out   = (float*)d_out;

    const int nvert  = in_sizes[0] / (CFEAT * 2);
    const int ntiles = (nvert + NV_TILE - 1) / NV_TILE;

    cudaFuncSetAttribute(onering_mma_kernel,
                         cudaFuncAttributeMaxDynamicSharedMemorySize, SMEM_TOTAL);

    int blocks = (ntiles < 148) ? ntiles : 148;
    onering_mma_kernel<<<blocks, THREADS, SMEM_TOTAL>>>(x, neigh, W, bias, out,
                                                        nvert, ntiles);
}

// round 8
// speedup vs baseline: 3.8492x; 1.2349x over previous
#include <cuda_runtime.h>
#include <cstdint>

// onering_conv via mma.sync tf32 (m16n8k8), v2: chunked/pipelined, no k-split.
// out[n,o,b] = sum_{k,c} x[idx[n*7+k], c, b] * W[o, k*64+c] + bias[o]
// Tile: 64 vertices -> A[128 x 448] (m = 2v+b) @ W^T -> D[128 x 64].
// K processed as 7 chunks of 64 (one per neighbor), A double-buffered in smem,
// gather LDGs for chunk c+1 issued before MMA of chunk c (latency overlap).
// 16 warps = 4m x 4n grid, warp tile 32x16, full-K register accumulation.
//
// Layout: column perm within 8-blocks p(w) = (w&3)*2 + (w>>2) makes fragment
// pairs (a0,a2),(a1,a3),(b0,b1) contiguous -> LDS.64; XOR swizzle ^((row&7)<<3)
// -> conflict-free LDS.64 / STS.64 (verified per 32-lane phase).

#define KNEI    7
#define CFEAT   64
#define OFEAT   64
#define NV_TILE 64
#define M_ROWS  128
#define KC      448
#define THREADS 512

#define SM_BIAS 0
#define SM_A    1024
#define ABUF    32768                       // 128 rows x 64 floats
#define SM_W    (SM_A + 2*ABUF)             // 66560
#define SMEM_TOTAL (SM_W + OFEAT*KC*4)      // 181248 <= 232448 opt-in
// Epilogue staging overlays A buf0 (128 x 64 floats = 32 KB)

static __device__ __forceinline__ float to_tf32(float x) {
    float r;
    asm("cvt.rna.tf32.f32 %0, %1;" : "=f"(r) : "f"(x));
    return r;
}
static __device__ __forceinline__ int colperm(int k) {
    return (k & ~7) | ((k & 3) << 1) | ((k >> 2) & 1);
}
static __device__ __forceinline__ void mma_tf32(float* d, float2 aA, float2 aB, float2 b) {
    asm volatile(
        "mma.sync.aligned.m16n8k8.row.col.f32.tf32.tf32.f32 "
        "{%0,%1,%2,%3}, {%4,%5,%6,%7}, {%8,%9}, {%0,%1,%2,%3};"
        : "+f"(d[0]), "+f"(d[1]), "+f"(d[2]), "+f"(d[3])
        : "r"(__float_as_uint(aA.x)), "r"(__float_as_uint(aB.x)),
          "r"(__float_as_uint(aA.y)), "r"(__float_as_uint(aB.y)),
          "r"(__float_as_uint(b.x)),  "r"(__float_as_uint(b.y)));
}

__global__ __launch_bounds__(THREADS, 1)
void onering_mma2_kernel(const float* __restrict__ x,
                         const int* __restrict__ neigh,
                         const float* __restrict__ W,
                         const float* __restrict__ bias,
                         float* __restrict__ out,
                         int nvert, int ntiles)
{
    extern __shared__ char smem[];
    float* bi_s = (float*)(smem + SM_BIAS);
    float* Ws   = (float*)(smem + SM_W);

    const int tid  = threadIdx.x;
    const int wid  = tid >> 5;
    const int lane = tid & 31;
    const int r    = lane >> 2;
    const int c    = lane & 3;

    const int wm = wid & 3;          // m-block (32 rows)
    const int wn = wid >> 2;         // n-block (16 cols)

    // ---- one-time: stage W (tf32, permuted + 8-way swizzled) + bias ----
    for (int j = tid; j < OFEAT * KC; j += THREADS) {
        int o = j / KC;
        int kcol = j - o * KC;
        int cp = colperm(kcol);
        Ws[o * KC + (cp ^ ((o & 7) << 3))] = to_tf32(W[j]);
    }
    if (tid < OFEAT) bi_s[tid] = bias[tid];
    __syncthreads();

    // ---- per-thread constants ----
    const int gv = tid >> 3;                 // gather vertex 0..63
    const int gq = tid & 7;                  // channel octet
    const int m0 = 2 * gv;
    const uint32_t swz0 = (uint32_t)(m0 & 7) << 3;
    const uint32_t swz1 = (uint32_t)((m0 + 1) & 7) << 3;
    const uint32_t gb0  = (uint32_t)m0 * 64;
    const uint32_t gb1  = gb0 + 64;
    const uint32_t q8   = (uint32_t)gq * 8;

    const uint32_t swzr = (uint32_t)r << 3;
    uint32_t aoff[4];                        // A frag rows: wm*32 + {0,8,16,24} + r
    #pragma unroll
    for (int h = 0; h < 4; h++) aoff[h] = (uint32_t)(wm * 32 + h * 8 + r) * 64;
    uint32_t boff[2];                        // W frag rows: wn*16 + g*8 + r
    #pragma unroll
    for (int g = 0; g < 2; g++) boff[g] = (uint32_t)(wn * 16 + g * 8 + r) * KC;

    for (int tile = blockIdx.x; tile < ntiles; tile += gridDim.x) {
        const int base = tile * NV_TILE;
        const int rem  = (nvert - base < NV_TILE) ? (nvert - base) : NV_TILE;
        const bool act = (gv < rem);
        const int* nb = neigh + (base + gv) * KNEI;

        float4 v0, v1, v2, v3;
        if (act) {   // load chunk 0
            int rown = nb[0];
            rown = (rown < 0) ? 0 : ((rown >= nvert) ? nvert - 1 : rown);
            const float4* src = (const float4*)(x + (size_t)rown * 128 + gq * 16);
            v0 = src[0]; v1 = src[1]; v2 = src[2]; v3 = src[3];
        }

        float acc[2][2][4];
        #pragma unroll
        for (int f = 0; f < 2; f++)
            #pragma unroll
            for (int g = 0; g < 2; g++)
                #pragma unroll
                for (int q = 0; q < 4; q++) acc[f][g][q] = 0.0f;

        #pragma unroll
        for (int ch = 0; ch < KNEI; ch++) {
            float*  Ab = (float*)(smem + SM_A + (ch & 1) * ABUF);
            float2* A2 = (float2*)Ab;

            // ---- STS chunk ch (8 STS.64, conflict-free) ----
            if (act) {
                A2[(gb0 + ((q8 + 0) ^ swz0)) >> 1] = make_float2(to_tf32(v0.x), to_tf32(v2.x));
                A2[(gb1 + ((q8 + 0) ^ swz1)) >> 1] = make_float2(to_tf32(v0.y), to_tf32(v2.y));
                A2[(gb0 + ((q8 + 2) ^ swz0)) >> 1] = make_float2(to_tf32(v0.z), to_tf32(v2.z));
                A2[(gb1 + ((q8 + 2) ^ swz1)) >> 1] = make_float2(to_tf32(v0.w), to_tf32(v2.w));
                A2[(gb0 + ((q8 + 4) ^ swz0)) >> 1] = make_float2(to_tf32(v1.x), to_tf32(v3.x));
                A2[(gb1 + ((q8 + 4) ^ swz1)) >> 1] = make_float2(to_tf32(v1.y), to_tf32(v3.y));
                A2[(gb0 + ((q8 + 6) ^ swz0)) >> 1] = make_float2(to_tf32(v1.z), to_tf32(v3.z));
                A2[(gb1 + ((q8 + 6) ^ swz1)) >> 1] = make_float2(to_tf32(v1.w), to_tf32(v3.w));
            }
            // ---- prefetch chunk ch+1 (LDG in flight across the MMA below) ----
            if (ch < KNEI - 1 && act) {
                int rown = nb[ch + 1];
                rown = (rown < 0) ? 0 : ((rown >= nvert) ? nvert - 1 : rown);
                const float4* src = (const float4*)(x + (size_t)rown * 128 + gq * 16);
                v0 = src[0]; v1 = src[1]; v2 = src[2]; v3 = src[3];
            }
            __syncthreads();   // buf (ch&1) fully written; also orders vs mma(ch-1) reads

            // ---- MMA on chunk ch: 8 ksteps x (6 LDS.64 + 4 mma) ----
            const float2* W2 = (const float2*)Ws;
            const uint32_t wch = (uint32_t)ch * 64;
            #pragma unroll
            for (int i = 0; i < 8; i++) {
                const uint32_t colp = (((uint32_t)(8 * i)) ^ swzr) + 2 * c;
                float2 fA[4];
                #pragma unroll
                for (int h = 0; h < 4; h++) fA[h] = A2[(aoff[h] + colp) >> 1];
                float2 fB[2];
                #pragma unroll
                for (int g = 0; g < 2; g++) fB[g] = W2[(boff[g] + wch + colp) >> 1];
                #pragma unroll
                for (int f = 0; f < 2; f++)
                    #pragma unroll
                    for (int g = 0; g < 2; g++)
                        mma_tf32(acc[f][g], fA[f * 2], fA[f * 2 + 1], fB[g]);
            }
        }
        __syncthreads();   // mma(chunk 6) done reading buf0 before Es overlays it

        // ---- epilogue: accs -> smem staging (overlay buf0) -> coalesced out ----
        float*  Es = (float*)(smem + SM_A);
        float2* E2 = (float2*)Es;
        #pragma unroll
        for (int f = 0; f < 2; f++) {
            #pragma unroll
            for (int g = 0; g < 2; g++) {
                int mA = wm * 32 + f * 16 + r;
                int mB = mA + 8;
                uint32_t n0 = (uint32_t)(wn * 16 + g * 8 + 2 * c);
                E2[((uint32_t)mA * 64 + (n0 ^ (((uint32_t)(mA & 7)) << 3))) >> 1] =
                    make_float2(acc[f][g][0], acc[f][g][1]);
                E2[((uint32_t)mB * 64 + (n0 ^ (((uint32_t)(mB & 7)) << 3))) >> 1] =
                    make_float2(acc[f][g][2], acc[f][g][3]);
            }
        }
        __syncthreads();
        // out float4 at lin: (o0,b0),(o0,b1),(o0+1,b0),(o0+1,b1); rows mA=2nl, mB=2nl+1
        for (int j = tid; j < rem * 32; j += THREADS) {
            int lin = j * 4;
            int nl  = lin >> 7;
            int o0  = (lin & 127) >> 1;
            int mA  = 2 * nl, mB = mA + 1;
            uint32_t sA = ((uint32_t)(mA & 7)) << 3;
            uint32_t sB = ((uint32_t)(mB & 7)) << 3;
            float b0v = bi_s[o0], b1v = bi_s[o0 + 1];
            float4 vv = make_float4(
                Es[mA * 64 + (((uint32_t)o0) ^ sA)]       + b0v,
                Es[mB * 64 + (((uint32_t)o0) ^ sB)]       + b0v,
                Es[mA * 64 + (((uint32_t)(o0 + 1)) ^ sA)] + b1v,
                Es[mB * 64 + (((uint32_t)(o0 + 1)) ^ sB)] + b1v);
            *(float4*)(out + (size_t)base * 128 + lin) = vv;
        }
        __syncthreads();   // Es / buf0 reused by next tile's gather
    }
}

extern "C" void kernel_launch(void* const* d_in, const int* in_sizes, int n_in,
                              void* d_out, int out_size)
{
    const float* x     = (const float*)d_in[0];
    const int*   neigh = (const int*)d_in[1];     // int32 (JAX canonicalization)
    const float* W     = (const float*)d_in[2];
    const float* bias  = (const float*)d_in[3];
    float*       out   = (float*)d_out;

    const int nvert  = in_sizes[0] / (CFEAT * 2);
    const int ntiles = (nvert + NV_TILE - 1) / NV_TILE;

    cudaFuncSetAttribute(onering_mma2_kernel,
                         cudaFuncAttributeMaxDynamicSharedMemorySize, SMEM_TOTAL);

    int blocks = (ntiles < 148) ? ntiles : 148;
    onering_mma2_kernel<<<blocks, THREADS, SMEM_TOTAL>>>(x, neigh, W, bias, out,
                                                         nvert, ntiles);
}

// round 12
// speedup vs baseline: 6.0027x; 1.5595x over previous
#include <cuda_runtime.h>
#include <cuda_fp16.h>
#include <cstdint>

// onering_conv via fp16 mma.sync m16n8k16 (f32 accumulate).
// out[n,o,b] = sum_{k,c} x[idx[n*7+k], c, b] * W[o, k*64+c] + bias[o]
// Tile: 64 vertices -> A[128 x 448] (m = 2v+b) @ W^T -> D[128 x 64].
// 7 chunks of k=64 (one per neighbor), A double-buffered, LDG prefetch with
// index loaded one chunk further ahead. 16 warps = 4m x 4n, warp tile 32x16.
//
// Layouts:
//  * within each 16-col block, perm p(j) = ((j&7)>>1)*4 + (j>>3)*2 + (j&1)
//    -> fragment pairs (a0,a2),(a1,a3),(b0,b1) contiguous => one LDS.64 each
//  * 16-col blocks XOR-swizzled by (row&3) -> conflict-free LDS.64 (per
//    16-lane phase) and STS.128 (per 8-lane phase); enumerated by hand.

#define KNEI    7
#define CFEAT   64
#define OFEAT   64
#define NV_TILE 64
#define KC      448
#define THREADS 512

#define SM_BIAS 0
#define SM_A    1024
#define ABUF    16384                       // 128 rows x 64 halves (128 B/row)
#define SM_W    (SM_A + 2*ABUF)             // 33792
#define SMEM_TOTAL (SM_W + OFEAT*KC*2)      // 91136
// Epilogue f32 staging (128 x 64 = 32768 B) overlays both A buffers exactly.

static __device__ __forceinline__ uint32_t h2u(float lo, float hi) {
    __half2 h = __floats2half2_rn(lo, hi);   // .x = lo (low 16 bits)
    return *reinterpret_cast<uint32_t*>(&h);
}
static __device__ __forceinline__ void mma_f16(float* d, uint32_t a0, uint32_t a1,
                                               uint32_t a2, uint32_t a3,
                                               uint32_t b0, uint32_t b1) {
    asm volatile(
        "mma.sync.aligned.m16n8k16.row.col.f32.f16.f16.f32 "
        "{%0,%1,%2,%3}, {%4,%5,%6,%7}, {%8,%9}, {%0,%1,%2,%3};"
        : "+f"(d[0]), "+f"(d[1]), "+f"(d[2]), "+f"(d[3])
        : "r"(a0), "r"(a1), "r"(a2), "r"(a3), "r"(b0), "r"(b1));
}

__global__ __launch_bounds__(THREADS, 1)
void onering_h16_kernel(const float* __restrict__ x,
                        const int* __restrict__ neigh,
                        const float* __restrict__ W,
                        const float* __restrict__ bias,
                        float* __restrict__ out,
                        int nvert, int ntiles)
{
    extern __shared__ char smem[];
    float* bi_s = (float*)(smem + SM_BIAS);
    __half* Ws  = (__half*)(smem + SM_W);

    const int tid  = threadIdx.x;
    const int wid  = tid >> 5;
    const int lane = tid & 31;
    const int r    = lane >> 2;
    const int c    = lane & 3;
    const int ra   = r & 3;

    const int wm = wid & 3;          // m-block (32 rows)
    const int wn = wid >> 2;         // n-block (16 cols)

    // ---- one-time: stage W as fp16, permuted + block-swizzled; bias ----
    for (int j = tid; j < OFEAT * KC; j += THREADS) {
        int o    = j / KC;
        int kcol = j - o * KC;
        int ch   = kcol >> 6;
        int t    = (kcol >> 4) & 3;
        int jj   = kcol & 15;
        int oh   = (((jj & 7) >> 1) << 2) | (((jj >> 3) & 1) << 1) | (jj & 1);
        int ph   = ch * 64 + ((t ^ (o & 3)) << 4) + oh;   // phys half within row
        Ws[o * KC + ph] = __float2half_rn(W[j]);
    }
    if (tid < OFEAT) bi_s[tid] = bias[tid];
    __syncthreads();

    // ---- per-thread constants ----
    // gather: thread = (vertex gv, phys-octet gq); phys halves [8gq, 8gq+8) of
    // rows m0, m0+1 come from x float4s {q0, q0+1, q0+4, q0+5}, q0 = 8t + 2s.
    const int gv = tid >> 3;
    const int gq = tid & 7;
    const int gs = gq & 1;
    const int gt = gq >> 1;
    const int q0 = 8 * gt + 2 * gs;
    const int m0 = 2 * gv;
    const uint32_t sts0 = (uint32_t)m0 * 128 + ((uint32_t)(gt ^ (m0 & 3)) << 5) + 16 * gs;
    const uint32_t sts1 = (uint32_t)(m0 + 1) * 128 +
                          ((uint32_t)(gt ^ ((m0 + 1) & 3)) << 5) + 16 * gs;

    uint32_t aB[4];                  // A frag byte base: rows wm*32 + h*8 + r
    #pragma unroll
    for (int h = 0; h < 4; h++) aB[h] = (uint32_t)(wm * 32 + h * 8 + r) * 128 + 8 * c;
    uint32_t bB[2];                  // W frag byte base: rows wn*16 + g*8 + r
    #pragma unroll
    for (int g = 0; g < 2; g++) bB[g] = (uint32_t)(wn * 16 + g * 8 + r) * (KC * 2) + 8 * c;

    for (int tile = blockIdx.x; tile < ntiles; tile += gridDim.x) {
        const int base = tile * NV_TILE;
        const int rem  = (nvert - base < NV_TILE) ? (nvert - base) : NV_TILE;
        const bool act = (gv < rem);
        const int* nb = neigh + (base + gv) * KNEI;

        float4 vA, vB, vC, vD;
        int ridx_next = 0;
        if (act) {
            int rown = nb[0];
            rown = (rown < 0) ? 0 : ((rown >= nvert) ? nvert - 1 : rown);
            const float4* src = (const float4*)(x + (size_t)rown * 128);
            vA = src[q0]; vB = src[q0 + 1]; vC = src[q0 + 4]; vD = src[q0 + 5];
            ridx_next = nb[1];      // index prefetched one chunk ahead
        }

        float acc[2][2][4];
        #pragma unroll
        for (int f = 0; f < 2; f++)
            #pragma unroll
            for (int g = 0; g < 2; g++)
                #pragma unroll
                for (int q = 0; q < 4; q++) acc[f][g][q] = 0.0f;

        #pragma unroll
        for (int ch = 0; ch < KNEI; ch++) {
            char* Ab = smem + SM_A + (ch & 1) * ABUF;

            // ---- STS chunk ch: 2x STS.128, conflict-free ----
            if (act) {
                uint4 u0 = make_uint4(h2u(vA.x, vA.z), h2u(vC.x, vC.z),
                                      h2u(vB.x, vB.z), h2u(vD.x, vD.z));
                uint4 u1 = make_uint4(h2u(vA.y, vA.w), h2u(vC.y, vC.w),
                                      h2u(vB.y, vB.w), h2u(vD.y, vD.w));
                *(uint4*)(Ab + sts0) = u0;
                *(uint4*)(Ab + sts1) = u1;
            }
            // ---- prefetch chunk ch+1 data (+ index for ch+2) ----
            if (ch < KNEI - 1 && act) {
                int rown = ridx_next;
                rown = (rown < 0) ? 0 : ((rown >= nvert) ? nvert - 1 : rown);
                if (ch < KNEI - 2) ridx_next = nb[ch + 2];
                const float4* src = (const float4*)(x + (size_t)rown * 128);
                vA = src[q0]; vB = src[q0 + 1]; vC = src[q0 + 4]; vD = src[q0 + 5];
            }
            __syncthreads();   // buf (ch&1) written; also orders vs mma(ch-1) reads

            // ---- MMA on chunk ch: 4 k16-steps x (6 LDS.64 + 4 mma) ----
            const char* Wc = (const char*)Ws + ch * 128;
            #pragma unroll
            for (int t = 0; t < 4; t++) {
                const uint32_t toff = (uint32_t)(t ^ ra) << 5;
                uint2 fA[4];
                #pragma unroll
                for (int h = 0; h < 4; h++) fA[h] = *(const uint2*)(Ab + aB[h] + toff);
                uint2 fB[2];
                #pragma unroll
                for (int g = 0; g < 2; g++) fB[g] = *(const uint2*)(Wc + bB[g] + toff);
                #pragma unroll
                for (int f = 0; f < 2; f++)
                    #pragma unroll
                    for (int g = 0; g < 2; g++)
                        mma_f16(acc[f][g],
                                fA[2 * f].x, fA[2 * f + 1].x,
                                fA[2 * f].y, fA[2 * f + 1].y,
                                fB[g].x, fB[g].y);
            }
        }
        __syncthreads();   // mma(chunk 6) done reading buf0 before Es overlays it

        // ---- epilogue: accs -> f32 staging (overlays A bufs) -> coalesced out ----
        float*  Es = (float*)(smem + SM_A);
        float2* E2 = (float2*)Es;
        #pragma unroll
        for (int f = 0; f < 2; f++) {
            #pragma unroll
            for (int g = 0; g < 2; g++) {
                int mA = wm * 32 + f * 16 + r;
                int mB = mA + 8;
                uint32_t n0 = (uint32_t)(wn * 16 + g * 8 + 2 * c);
                E2[((uint32_t)mA * 64 + (n0 ^ (((uint32_t)(mA & 7)) << 3))) >> 1] =
                    make_float2(acc[f][g][0], acc[f][g][1]);
                E2[((uint32_t)mB * 64 + (n0 ^ (((uint32_t)(mB & 7)) << 3))) >> 1] =
                    make_float2(acc[f][g][2], acc[f][g][3]);
            }
        }
        __syncthreads();
        // out float4 at lin: (o0,b0),(o0,b1),(o0+1,b0),(o0+1,b1); rows 2nl, 2nl+1
        for (int j = tid; j < rem * 32; j += THREADS) {
            int lin = j * 4;
            int nl  = lin >> 7;
            int o0  = (lin & 127) >> 1;
            int mA  = 2 * nl, mB = mA + 1;
            uint32_t sA = ((uint32_t)(mA & 7)) << 3;
            uint32_t sB = ((uint32_t)(mB & 7)) << 3;
            float b0v = bi_s[o0], b1v = bi_s[o0 + 1];
            float4 vv = make_float4(
                Es[mA * 64 + (((uint32_t)o0) ^ sA)]       + b0v,
                Es[mB * 64 + (((uint32_t)o0) ^ sB)]       + b0v,
                Es[mA * 64 + (((uint32_t)(o0 + 1)) ^ sA)] + b1v,
                Es[mB * 64 + (((uint32_t)(o0 + 1)) ^ sB)] + b1v);
            *(float4*)(out + (size_t)base * 128 + lin) = vv;
        }
        __syncthreads();   // staging / A bufs reused by next tile's gather
    }
}

extern "C" void kernel_launch(void* const* d_in, const int* in_sizes, int n_in,
                              void* d_out, int out_size)
{
    const float* x     = (const float*)d_in[0];
    const int*   neigh = (const int*)d_in[1];     // int32 (JAX canonicalization)
    const float* W     = (const float*)d_in[2];
    const float* bias  = (const float*)d_in[3];
    float*       out   = (float*)d_out;

    const int nvert  = in_sizes[0] / (CFEAT * 2);
    const int ntiles = (nvert + NV_TILE - 1) / NV_TILE;

    cudaFuncSetAttribute(onering_h16_kernel,
                         cudaFuncAttributeMaxDynamicSharedMemorySize, SMEM_TOTAL);

    int blocks = (ntiles < 148) ? ntiles : 148;
    onering_h16_kernel<<<blocks, THREADS, SMEM_TOTAL>>>(x, neigh, W, bias, out,
                                                        nvert, ntiles);
}

// round 16
// speedup vs baseline: 7.3921x; 1.2315x over previous
#include <cuda_runtime.h>
#include <cuda_fp16.h>
#include <cstdint>

// onering_conv via fp16 mma.sync m16n8k16 (f32 accumulate), v4 (resubmit; R15
// failure was harness device-init, kernel never ran):
//  - 256-thread CTAs, 2 CTAs/SM (occupancy doubled; sync bubbles overlap)
//  - warp tile 32x32 (4m x 2n warps): 8 LDS.64 feed 8 MMAs per k16-step
//    (1.5x less smem crossbar traffic than 32x16 tiles)
// out[n,o,b] = sum_{k,c} x[idx[n*7+k], c, b] * W[o, k*64+c] + bias[o]
// Tile: 64 vertices -> A[128 x 448] (m = 2v+b) @ W^T -> D[128 x 64].
// 7 chunks of k=64 (one per neighbor), A double-buffered, register prefetch.
//
// Layouts (verified in earlier rounds, unchanged):
//  * within each 16-col block, perm p(j) = ((j&7)>>1)*4 + (j>>3)*2 + (j&1)
//    -> fragment pairs contiguous => LDS.64
//  * 16-col blocks (32B) XOR-swizzled by (row&3) -> conflict-free LDS.64/STS.128

#define KNEI    7
#define CFEAT   64
#define OFEAT   64
#define NV_TILE 64
#define KC      448
#define THREADS 256

#define SM_BIAS 0
#define SM_A    1024
#define ABUF    16384                       // 128 rows x 64 halves (128 B/row)
#define SM_W    (SM_A + 2*ABUF)             // 33792
#define SMEM_TOTAL (SM_W + OFEAT*KC*2)      // 91136 (x2 CTAs = 182272 <= 228K)
// Epilogue f32 staging (128 x 64 = 32768 B) overlays both A buffers exactly.

static __device__ __forceinline__ uint32_t h2u(float lo, float hi) {
    __half2 h = __floats2half2_rn(lo, hi);
    return *reinterpret_cast<uint32_t*>(&h);
}
static __device__ __forceinline__ void mma_f16(float* d, uint32_t a0, uint32_t a1,
                                               uint32_t a2, uint32_t a3,
                                               uint32_t b0, uint32_t b1) {
    asm volatile(
        "mma.sync.aligned.m16n8k16.row.col.f32.f16.f16.f32 "
        "{%0,%1,%2,%3}, {%4,%5,%6,%7}, {%8,%9}, {%0,%1,%2,%3};"
        : "+f"(d[0]), "+f"(d[1]), "+f"(d[2]), "+f"(d[3])
        : "r"(a0), "r"(a1), "r"(a2), "r"(a3), "r"(b0), "r"(b1));
}
static __device__ __forceinline__ int clampi(int v, int n) {
    return (v < 0) ? 0 : ((v >= n) ? n - 1 : v);
}

__global__ __launch_bounds__(THREADS, 2)
void onering_h16b_kernel(const float* __restrict__ x,
                         const int* __restrict__ neigh,
                         const float* __restrict__ W,
                         const float* __restrict__ bias,
                         float* __restrict__ out,
                         int nvert, int ntiles)
{
    extern __shared__ char smem[];
    float* bi_s = (float*)(smem + SM_BIAS);
    __half* Ws  = (__half*)(smem + SM_W);

    const int tid  = threadIdx.x;
    const int wid  = tid >> 5;
    const int lane = tid & 31;
    const int r    = lane >> 2;
    const int c    = lane & 3;
    const int ra   = r & 3;

    const int wm = wid & 3;          // m-block (32 rows)
    const int wn = wid >> 2;         // n-block (32 cols), 0..1

    // ---- one-time: stage W as fp16 (permuted + block-swizzled) + bias ----
    for (int j = tid; j < OFEAT * KC; j += THREADS) {
        int o    = j / KC;
        int kcol = j - o * KC;
        int ch   = kcol >> 6;
        int t    = (kcol >> 4) & 3;
        int jj   = kcol & 15;
        int oh   = (((jj & 7) >> 1) << 2) | (((jj >> 3) & 1) << 1) | (jj & 1);
        int ph   = ch * 64 + ((t ^ (o & 3)) << 4) + oh;
        Ws[o * KC + ph] = __float2half_rn(W[j]);
    }
    if (tid < OFEAT) bi_s[tid] = bias[tid];
    __syncthreads();

    // ---- per-thread constants ----
    // gather: two passes; pass p handles vertex gvb + 32p, phys-octet gq.
    const int gvb = tid >> 3;                // 0..31
    const int gq  = tid & 7;
    const int gs  = gq & 1;
    const int gt  = gq >> 1;
    const int q0  = 8 * gt + 2 * gs;
    const int m0  = 2 * gvb;
    const uint32_t sts0 = (uint32_t)m0 * 128 + ((uint32_t)(gt ^ (m0 & 3)) << 5) + 16 * gs;
    const uint32_t sts1 = (uint32_t)(m0 + 1) * 128 +
                          ((uint32_t)(gt ^ ((m0 + 1) & 3)) << 5) + 16 * gs;
    // pass1 rows are +64 -> +8192 bytes; (m&3) unchanged, swizzle identical.

    uint32_t aB[4];                  // A frag byte base: rows wm*32 + h*8 + r
    #pragma unroll
    for (int h = 0; h < 4; h++) aB[h] = (uint32_t)(wm * 32 + h * 8 + r) * 128 + 8 * c;
    uint32_t bB[4];                  // W frag byte base: rows wn*32 + g*8 + r
    #pragma unroll
    for (int g = 0; g < 4; g++) bB[g] = (uint32_t)(wn * 32 + g * 8 + r) * (KC * 2) + 8 * c;

    for (int tile = blockIdx.x; tile < ntiles; tile += gridDim.x) {
        const int base = tile * NV_TILE;
        const int rem  = (nvert - base < NV_TILE) ? (nvert - base) : NV_TILE;
        const bool act0 = (gvb < rem);
        const bool act1 = (gvb + 32 < rem);
        const int* nb0 = neigh + (base + gvb) * KNEI;
        const int* nb1 = nb0 + 32 * KNEI;

        float4 P0[4], P1[4];
        int nx0 = 0, nx1 = 0;
        if (act0) {
            const float4* src = (const float4*)(x + (size_t)clampi(nb0[0], nvert) * 128);
            P0[0] = src[q0]; P0[1] = src[q0 + 1]; P0[2] = src[q0 + 4]; P0[3] = src[q0 + 5];
            nx0 = nb0[1];
        }
        if (act1) {
            const float4* src = (const float4*)(x + (size_t)clampi(nb1[0], nvert) * 128);
            P1[0] = src[q0]; P1[1] = src[q0 + 1]; P1[2] = src[q0 + 4]; P1[3] = src[q0 + 5];
            nx1 = nb1[1];
        }

        float acc[2][4][4];
        #pragma unroll
        for (int f = 0; f < 2; f++)
            #pragma unroll
            for (int g = 0; g < 4; g++)
                #pragma unroll
                for (int q = 0; q < 4; q++) acc[f][g][q] = 0.0f;

        #pragma unroll
        for (int ch = 0; ch < KNEI; ch++) {
            char* Ab = smem + SM_A + (ch & 1) * ABUF;

            // ---- STS chunk ch: 2x STS.128 per active pass, conflict-free ----
            if (act0) {
                *(uint4*)(Ab + sts0) = make_uint4(h2u(P0[0].x, P0[0].z), h2u(P0[2].x, P0[2].z),
                                                  h2u(P0[1].x, P0[1].z), h2u(P0[3].x, P0[3].z));
                *(uint4*)(Ab + sts1) = make_uint4(h2u(P0[0].y, P0[0].w), h2u(P0[2].y, P0[2].w),
                                                  h2u(P0[1].y, P0[1].w), h2u(P0[3].y, P0[3].w));
            }
            if (act1) {
                *(uint4*)(Ab + sts0 + 8192) = make_uint4(h2u(P1[0].x, P1[0].z), h2u(P1[2].x, P1[2].z),
                                                         h2u(P1[1].x, P1[1].z), h2u(P1[3].x, P1[3].z));
                *(uint4*)(Ab + sts1 + 8192) = make_uint4(h2u(P1[0].y, P1[0].w), h2u(P1[2].y, P1[2].w),
                                                         h2u(P1[1].y, P1[1].w), h2u(P1[3].y, P1[3].w));
            }
            // ---- prefetch chunk ch+1 (indices one chunk further ahead) ----
            if (ch < KNEI - 1) {
                if (act0) {
                    const float4* src = (const float4*)(x + (size_t)clampi(nx0, nvert) * 128);
                    if (ch < KNEI - 2) nx0 = nb0[ch + 2];
                    P0[0] = src[q0]; P0[1] = src[q0 + 1]; P0[2] = src[q0 + 4]; P0[3] = src[q0 + 5];
                }
                if (act1) {
                    const float4* src = (const float4*)(x + (size_t)clampi(nx1, nvert) * 128);
                    if (ch < KNEI - 2) nx1 = nb1[ch + 2];
                    P1[0] = src[q0]; P1[1] = src[q0 + 1]; P1[2] = src[q0 + 4]; P1[3] = src[q0 + 5];
                }
            }
            __syncthreads();   // buf (ch&1) written; also orders vs mma(ch-1) reads

            // ---- MMA on chunk ch: 4 k16-steps x (8 LDS.64 + 8 mma) ----
            const char* Wc = (const char*)Ws + ch * 128;
            #pragma unroll
            for (int t = 0; t < 4; t++) {
                const uint32_t toff = (uint32_t)(t ^ ra) << 5;
                uint2 fA[4];
                #pragma unroll
                for (int h = 0; h < 4; h++) fA[h] = *(const uint2*)(Ab + aB[h] + toff);
                uint2 fB[4];
                #pragma unroll
                for (int g = 0; g < 4; g++) fB[g] = *(const uint2*)(Wc + bB[g] + toff);
                #pragma unroll
                for (int f = 0; f < 2; f++)
                    #pragma unroll
                    for (int g = 0; g < 4; g++)
                        mma_f16(acc[f][g],
                                fA[2 * f].x, fA[2 * f + 1].x,
                                fA[2 * f].y, fA[2 * f + 1].y,
                                fB[g].x, fB[g].y);
            }
        }
        __syncthreads();   // mma(chunk 6) done reading buf0 before Es overlays it

        // ---- epilogue: accs -> f32 staging (overlays A bufs) -> coalesced out ----
        float2* E2 = (float2*)(smem + SM_A);
        #pragma unroll
        for (int f = 0; f < 2; f++) {
            #pragma unroll
            for (int g = 0; g < 4; g++) {
                int mA = wm * 32 + f * 16 + r;
                int mB = mA + 8;
                uint32_t n0 = (uint32_t)(wn * 32 + g * 8 + 2 * c);
                E2[((uint32_t)mA * 64 + (n0 ^ (((uint32_t)(mA & 7)) << 3))) >> 1] =
                    make_float2(acc[f][g][0], acc[f][g][1]);
                E2[((uint32_t)mB * 64 + (n0 ^ (((uint32_t)(mB & 7)) << 3))) >> 1] =
                    make_float2(acc[f][g][2], acc[f][g][3]);
            }
        }
        __syncthreads();
        // out float4 at lin: (o0,b0),(o0,b1),(o0+1,b0),(o0+1,b1); rows 2nl, 2nl+1
        {
            const float* Es = (const float*)(smem + SM_A);
            for (int j = tid; j < rem * 32; j += THREADS) {
                int lin = j * 4;
                int nl  = lin >> 7;
                int o0  = (lin & 127) >> 1;
                int mA  = 2 * nl, mB = mA + 1;
                uint32_t sA = ((uint32_t)(mA & 7)) << 3;
                uint32_t sB = ((uint32_t)(mB & 7)) << 3;
                float b0v = bi_s[o0], b1v = bi_s[o0 + 1];
                float4 vv = make_float4(
                    Es[mA * 64 + (((uint32_t)o0) ^ sA)]       + b0v,
                    Es[mB * 64 + (((uint32_t)o0) ^ sB)]       + b0v,
                    Es[mA * 64 + (((uint32_t)(o0 + 1)) ^ sA)] + b1v,
                    Es[mB * 64 + (((uint32_t)(o0 + 1)) ^ sB)] + b1v);
                *(float4*)(out + (size_t)base * 128 + lin) = vv;
            }
        }
        __syncthreads();   // staging / A bufs reused by next tile's gather
    }
}

extern "C" void kernel_launch(void* const* d_in, const int* in_sizes, int n_in,
                              void* d_out, int out_size)
{
    const float* x     = (const float*)d_in[0];
    const int*   neigh = (const int*)d_in[1];     // int32 (JAX canonicalization)
    const float* W     = (const float*)d_in[2];
    const float* bias  = (const float*)d_in[3];
    float*       out   = (float*)d_out;

    const int nvert  = in_sizes[0] / (CFEAT * 2);
    const int ntiles = (nvert + NV_TILE - 1) / NV_TILE;

    cudaFuncSetAttribute(onering_h16b_kernel,
                         cudaFuncAttributeMaxDynamicSharedMemorySize, SMEM_TOTAL);

    // 2 CTAs per SM
    int blocks = (ntiles < 296) ? ntiles : 296;
    onering_h16b_kernel<<<blocks, THREADS, SMEM_TOTAL>>>(x, neigh, W, bias, out,
                                                         nvert, ntiles);
}